// round 2
// baseline (speedup 1.0000x reference)
#include <cuda_runtime.h>
#include <cuda_bf16.h>
#include <cstddef>

// Problem constants (shapes fixed by the dataset; N/E taken from in_sizes at runtime)
#define MAXN 50000
#define MAXE 800000

// ---------------- scratch (device globals; no allocs allowed) ----------------
__device__ int   g_deg[MAXN];
__device__ int   g_rowptr[MAXN + 1];
__device__ int   g_fill[MAXN];
__device__ int   g_col[MAXE];

__device__ float g_h1[(size_t)MAXN * 256];     // layer1 linear out
__device__ float g_hrelu[(size_t)MAXN * 256];  // layer1 GAT out (post relu)
__device__ float g_h2[(size_t)MAXN * 64];      // layer2 linear out
__device__ float g_as1[MAXN * 4], g_ad1[MAXN * 4];
__device__ float g_as2[MAXN],     g_ad2[MAXN];

// ---------------- CSR build ----------------
__global__ void k_zero_deg(int N) {
    int i = blockIdx.x * blockDim.x + threadIdx.x;
    if (i < N) g_deg[i] = 0;
}

__global__ void k_hist(const int* __restrict__ dst, int E, int N) {
    int i = blockIdx.x * blockDim.x + threadIdx.x;
    if (i < E) {
        int d = dst[i];
        if (d >= 0 && d < N) atomicAdd(&g_deg[d], 1);
    }
}

// single-block exclusive scan of g_deg -> g_rowptr (and g_fill copy)
__global__ void k_scan(int N) {
    __shared__ int sh[1024];
    int t = threadIdx.x;
    int carry = 0;
    for (int base = 0; base < N; base += 1024) {
        int i = base + t;
        int v = (i < N) ? g_deg[i] : 0;
        sh[t] = v;
        __syncthreads();
        #pragma unroll
        for (int off = 1; off < 1024; off <<= 1) {
            int x = (t >= off) ? sh[t - off] : 0;
            __syncthreads();
            sh[t] += x;
            __syncthreads();
        }
        int excl = carry + sh[t] - v;
        if (i < N) { g_rowptr[i] = excl; g_fill[i] = excl; }
        carry += sh[1023];
        __syncthreads();
    }
    if (t == 0) g_rowptr[N] = carry;
}

__global__ void k_scatter(const int* __restrict__ src,
                          const int* __restrict__ dst, int E, int N) {
    int i = blockIdx.x * blockDim.x + threadIdx.x;
    if (i < E) {
        int d = dst[i];
        if (d >= 0 && d < N) {
            int pos = atomicAdd(&g_fill[d], 1);
            g_col[pos] = src[i];
        }
    }
}

// ---------------- SGEMM: C[M,N] = A[M,K] @ B[K,N], row-major, fp32 ----------------
// 64x64 tile, BK=16, 256 threads, 4x4 microtile, float4 loads.
__global__ void k_sgemm(const float* __restrict__ A, const float* __restrict__ B,
                        float* __restrict__ C, int M, int N, int K) {
    __shared__ float As[16][68];   // transposed A tile; pitch 68 floats = 272B (16B aligned)
    __shared__ float Bs[16][64];
    int tid = threadIdx.x;
    int tx = tid & 15, ty = tid >> 4;
    int row0 = blockIdx.y * 64, col0 = blockIdx.x * 64;
    int ar = tid >> 2, ak = (tid & 3) * 4;   // A load: row in tile, k (float4)
    int bk = tid >> 4, bc = (tid & 15) * 4;  // B load

    float acc[4][4];
    #pragma unroll
    for (int i = 0; i < 4; i++)
        #pragma unroll
        for (int j = 0; j < 4; j++) acc[i][j] = 0.f;

    for (int k0 = 0; k0 < K; k0 += 16) {
        float4 av = make_float4(0.f, 0.f, 0.f, 0.f);
        int arow = row0 + ar;
        if (arow < M) av = *(const float4*)(A + (size_t)arow * K + k0 + ak);
        As[ak + 0][ar] = av.x; As[ak + 1][ar] = av.y;
        As[ak + 2][ar] = av.z; As[ak + 3][ar] = av.w;
        *(float4*)(&Bs[bk][bc]) = *(const float4*)(B + (size_t)(k0 + bk) * N + col0 + bc);
        __syncthreads();
        #pragma unroll
        for (int k = 0; k < 16; k++) {
            float4 a4 = *(const float4*)&As[k][ty * 4];
            float4 b4 = *(const float4*)&Bs[k][tx * 4];
            float a[4] = {a4.x, a4.y, a4.z, a4.w};
            float b[4] = {b4.x, b4.y, b4.z, b4.w};
            #pragma unroll
            for (int i = 0; i < 4; i++)
                #pragma unroll
                for (int j = 0; j < 4; j++) acc[i][j] += a[i] * b[j];
        }
        __syncthreads();
    }
    #pragma unroll
    for (int i = 0; i < 4; i++) {
        int row = row0 + ty * 4 + i;
        if (row < M) {
            float4 o = make_float4(acc[i][0], acc[i][1], acc[i][2], acc[i][3]);
            *(float4*)(C + (size_t)row * N + col0 + tx * 4) = o;
        }
    }
}

// ---------------- attention coefficients ----------------
// layer1: per node, 4 heads x 64 dims. warp per node.
__global__ void k_alpha1(const float* __restrict__ aw_s, const float* __restrict__ aw_d, int N) {
    int gt = blockIdx.x * blockDim.x + threadIdx.x;
    int n = gt >> 5, lane = gt & 31;
    if (n >= N) return;
    const float* hrow = g_h1 + (size_t)n * 256;
    float ps[4] = {0.f, 0.f, 0.f, 0.f}, pd[4] = {0.f, 0.f, 0.f, 0.f};
    #pragma unroll
    for (int r = 0; r < 8; r++) {
        float v = hrow[r * 32 + lane];
        int h = r >> 1;
        int cc = (r & 1) * 32 + lane;
        ps[h] += v * aw_s[h * 64 + cc];
        pd[h] += v * aw_d[h * 64 + cc];
    }
    #pragma unroll
    for (int h = 0; h < 4; h++) {
        float s = ps[h], d = pd[h];
        #pragma unroll
        for (int off = 16; off; off >>= 1) {
            s += __shfl_xor_sync(0xffffffffu, s, off);
            d += __shfl_xor_sync(0xffffffffu, d, off);
        }
        if (lane == 0) { g_as1[n * 4 + h] = s; g_ad1[n * 4 + h] = d; }
    }
}

// layer2: 1 head x 64 dims
__global__ void k_alpha2(const float* __restrict__ aw_s, const float* __restrict__ aw_d, int N) {
    int gt = blockIdx.x * blockDim.x + threadIdx.x;
    int n = gt >> 5, lane = gt & 31;
    if (n >= N) return;
    const float* hrow = g_h2 + (size_t)n * 64;
    float v0 = hrow[lane], v1 = hrow[lane + 32];
    float s = v0 * aw_s[lane] + v1 * aw_s[lane + 32];
    float d = v0 * aw_d[lane] + v1 * aw_d[lane + 32];
    #pragma unroll
    for (int off = 16; off; off >>= 1) {
        s += __shfl_xor_sync(0xffffffffu, s, off);
        d += __shfl_xor_sync(0xffffffffu, d, off);
    }
    if (lane == 0) { g_as2[n] = s; g_ad2[n] = d; }
}

// ---------------- aggregation (warp per dst node, CSR gather, no atomics) ----------------
// layer1: 256 channels. lane covers float4 at c=lane*4 (head lane>>4) and c=128+lane*4 (head 2+lane>>4).
__global__ void k_agg1(const float* __restrict__ b1, int N) {
    int gt = blockIdx.x * blockDim.x + threadIdx.x;
    int n = gt >> 5, lane = gt & 31;
    if (n >= N) return;
    int h0 = lane >> 4, h1 = h0 + 2;
    float ad0 = g_ad1[n * 4 + h0];
    float ad1v = g_ad1[n * 4 + h1];
    const float4* H = (const float4*)g_h1;
    float4 acc0 = make_float4(0.f, 0.f, 0.f, 0.f), acc1 = acc0;
    float s0 = 0.f, s1 = 0.f;
    int beg = g_rowptr[n], end = g_rowptr[n + 1];
    for (int e = beg - 1; e < end; e++) {            // e == beg-1 -> self loop
        int src = (e < beg) ? n : g_col[e];
        float t0 = g_as1[src * 4 + h0] + ad0;  t0 = (t0 > 0.f) ? t0 : 0.2f * t0;
        float t1 = g_as1[src * 4 + h1] + ad1v; t1 = (t1 > 0.f) ? t1 : 0.2f * t1;
        float x0 = __expf(t0), x1 = __expf(t1);
        float4 v0 = H[(size_t)src * 64 + lane];
        float4 v1 = H[(size_t)src * 64 + 32 + lane];
        acc0.x += x0 * v0.x; acc0.y += x0 * v0.y; acc0.z += x0 * v0.z; acc0.w += x0 * v0.w;
        acc1.x += x1 * v1.x; acc1.y += x1 * v1.y; acc1.z += x1 * v1.z; acc1.w += x1 * v1.w;
        s0 += x0; s1 += x1;
    }
    float i0 = 1.f / s0, i1 = 1.f / s1;
    int c0 = lane * 4, c1 = 128 + lane * 4;
    float4 o0, o1;
    o0.x = fmaxf(acc0.x * i0 + b1[c0 + 0], 0.f);
    o0.y = fmaxf(acc0.y * i0 + b1[c0 + 1], 0.f);
    o0.z = fmaxf(acc0.z * i0 + b1[c0 + 2], 0.f);
    o0.w = fmaxf(acc0.w * i0 + b1[c0 + 3], 0.f);
    o1.x = fmaxf(acc1.x * i1 + b1[c1 + 0], 0.f);
    o1.y = fmaxf(acc1.y * i1 + b1[c1 + 1], 0.f);
    o1.z = fmaxf(acc1.z * i1 + b1[c1 + 2], 0.f);
    o1.w = fmaxf(acc1.w * i1 + b1[c1 + 3], 0.f);
    float4* O = (float4*)g_hrelu;
    O[(size_t)n * 64 + lane] = o0;
    O[(size_t)n * 64 + 32 + lane] = o1;
}

// layer2: 64 channels, 1 head. lane covers float2 at c=lane*2.
__global__ void k_agg2(const float* __restrict__ b2, float* __restrict__ out, int N) {
    int gt = blockIdx.x * blockDim.x + threadIdx.x;
    int n = gt >> 5, lane = gt & 31;
    if (n >= N) return;
    float ad = g_ad2[n];
    const float2* H = (const float2*)g_h2;
    float2 acc = make_float2(0.f, 0.f);
    float s = 0.f;
    int beg = g_rowptr[n], end = g_rowptr[n + 1];
    for (int e = beg - 1; e < end; e++) {
        int src = (e < beg) ? n : g_col[e];
        float t = g_as2[src] + ad; t = (t > 0.f) ? t : 0.2f * t;
        float x = __expf(t);
        float2 v = H[(size_t)src * 32 + lane];
        acc.x += x * v.x; acc.y += x * v.y;
        s += x;
    }
    float inv = 1.f / s;
    float2 o;
    o.x = acc.x * inv + b2[lane * 2 + 0];
    o.y = acc.y * inv + b2[lane * 2 + 1];
    ((float2*)out)[(size_t)n * 32 + lane] = o;
}

// ---------------- launch ----------------
extern "C" void kernel_launch(void* const* d_in, const int* in_sizes, int n_in,
                              void* d_out, int out_size) {
    const float* x    = (const float*)d_in[0];
    const int*   ei   = (const int*)d_in[1];     // edge_index delivered as int32
    const float* W1   = (const float*)d_in[2];
    const float* as1w = (const float*)d_in[3];
    const float* ad1w = (const float*)d_in[4];
    const float* b1   = (const float*)d_in[5];
    const float* W2   = (const float*)d_in[6];
    const float* as2w = (const float*)d_in[7];
    const float* ad2w = (const float*)d_in[8];
    const float* b2   = (const float*)d_in[9];

    int N = in_sizes[0] / 128;
    int E = in_sizes[1] / 2;
    const int* srcp = ei;
    const int* dstp = ei + E;

    void *p_h1, *p_hrelu, *p_h2;
    cudaGetSymbolAddress(&p_h1, g_h1);
    cudaGetSymbolAddress(&p_hrelu, g_hrelu);
    cudaGetSymbolAddress(&p_h2, g_h2);

    // CSR build (by dst; self-loops handled implicitly in aggregation)
    k_zero_deg<<<(N + 255) / 256, 256>>>(N);
    k_hist<<<(E + 255) / 256, 256>>>(dstp, E, N);
    k_scan<<<1, 1024>>>(N);
    k_scatter<<<(E + 255) / 256, 256>>>(srcp, dstp, E, N);

    // layer 1
    dim3 g1(256 / 64, (N + 63) / 64);
    k_sgemm<<<g1, 256>>>(x, W1, (float*)p_h1, N, 256, 128);
    k_alpha1<<<(N * 32 + 255) / 256, 256>>>(as1w, ad1w, N);
    k_agg1<<<(N * 32 + 255) / 256, 256>>>(b1, N);

    // layer 2
    dim3 g2(64 / 64, (N + 63) / 64);
    k_sgemm<<<g2, 256>>>((const float*)p_hrelu, W2, (float*)p_h2, N, 64, 256);
    k_alpha2<<<(N * 32 + 255) / 256, 256>>>(as2w, ad2w, N);
    k_agg2<<<(N * 32 + 255) / 256, 256>>>(b2, (float*)d_out, N);
}

// round 3
// speedup vs baseline: 1.0597x; 1.0597x over previous
#include <cuda_runtime.h>
#include <cuda_bf16.h>
#include <cstddef>

#define MAXN 50000
#define MAXE 800000

// ---------------- scratch (device globals; no allocs allowed) ----------------
__device__ int   g_deg[MAXN];
__device__ int   g_rowptr[MAXN + 1];
__device__ int   g_fill[MAXN];
__device__ int   g_col[MAXE];

__device__ float g_h1[(size_t)MAXN * 256];     // layer1 linear out
__device__ float g_hrelu[(size_t)MAXN * 256];  // layer1 GAT out (post relu)
__device__ float g_h2[(size_t)MAXN * 64];      // layer2 linear out
__device__ float g_as1[MAXN * 4], g_ad1[MAXN * 4];
__device__ float g_as2[MAXN],     g_ad2[MAXN];

// ---------------- CSR build ----------------
__global__ void k_zero_deg(int N) {
    int i = blockIdx.x * blockDim.x + threadIdx.x;
    if (i < N) g_deg[i] = 0;
}

__global__ void k_hist(const int* __restrict__ dst, int E, int N) {
    int i = blockIdx.x * blockDim.x + threadIdx.x;
    if (i < E) {
        int d = dst[i];
        if (d >= 0 && d < N) atomicAdd(&g_deg[d], 1);
    }
}

__global__ void k_scan(int N) {
    __shared__ int sh[1024];
    int t = threadIdx.x;
    int carry = 0;
    for (int base = 0; base < N; base += 1024) {
        int i = base + t;
        int v = (i < N) ? g_deg[i] : 0;
        sh[t] = v;
        __syncthreads();
        #pragma unroll
        for (int off = 1; off < 1024; off <<= 1) {
            int x = (t >= off) ? sh[t - off] : 0;
            __syncthreads();
            sh[t] += x;
            __syncthreads();
        }
        int excl = carry + sh[t] - v;
        if (i < N) { g_rowptr[i] = excl; g_fill[i] = excl; }
        carry += sh[1023];
        __syncthreads();
    }
    if (t == 0) g_rowptr[N] = carry;
}

__global__ void k_scatter(const int* __restrict__ src,
                          const int* __restrict__ dst, int E, int N) {
    int i = blockIdx.x * blockDim.x + threadIdx.x;
    if (i < E) {
        int d = dst[i];
        if (d >= 0 && d < N) {
            int pos = atomicAdd(&g_fill[d], 1);
            g_col[pos] = src[i];
        }
    }
}

// ---------------- SGEMM: C[M,N] = A[M,K] @ B[K,N], row-major fp32 ----------------
// 128x64 tile, BK=16, 256 threads, 8x4 microtile, double-buffered smem.
// K must be a multiple of 16, N a multiple of 64.
__global__ void __launch_bounds__(256, 2)
k_sgemm(const float* __restrict__ A, const float* __restrict__ B,
        float* __restrict__ C, int M, int N, int K) {
    __shared__ float As[2][16][132];   // pitch 132: 16B-aligned rows, 2-way store conflict only
    __shared__ float Bs[2][16][64];

    int tid = threadIdx.x;
    int row0 = blockIdx.y * 128, col0 = blockIdx.x * 64;

    // A loader: 512 float4 per tile, 2 per thread.  row = p*64 + tid/4, k4 = tid%4
    int aRow = tid >> 2, aK = (tid & 3) * 4;
    // B loader: 256 float4 per tile, 1 per thread.
    int bRow = tid >> 4, bCol = (tid & 15) * 4;
    // compute map
    int ty = tid >> 4;           // 0..15 -> rows ty*8..ty*8+7
    int tx = tid & 15;           // 0..15 -> cols tx*4..tx*4+3

    float acc[8][4];
    #pragma unroll
    for (int i = 0; i < 8; i++)
        #pragma unroll
        for (int j = 0; j < 4; j++) acc[i][j] = 0.f;

    int nk = K >> 4;
    float4 aReg[2], bReg;

    // prologue: load tile 0
    #pragma unroll
    for (int p = 0; p < 2; p++) {
        int r = row0 + aRow + p * 64;
        aReg[p] = (r < M) ? *(const float4*)(A + (size_t)r * K + aK)
                          : make_float4(0.f, 0.f, 0.f, 0.f);
    }
    bReg = *(const float4*)(B + (size_t)bRow * N + col0 + bCol);
    #pragma unroll
    for (int p = 0; p < 2; p++) {
        int r = aRow + p * 64;
        As[0][aK + 0][r] = aReg[p].x; As[0][aK + 1][r] = aReg[p].y;
        As[0][aK + 2][r] = aReg[p].z; As[0][aK + 3][r] = aReg[p].w;
    }
    *(float4*)(&Bs[0][bRow][bCol]) = bReg;
    __syncthreads();

    for (int t = 0; t < nk; t++) {
        int buf = t & 1;
        int nxt = t + 1;
        if (nxt < nk) {
            int k0 = nxt << 4;
            #pragma unroll
            for (int p = 0; p < 2; p++) {
                int r = row0 + aRow + p * 64;
                aReg[p] = (r < M) ? *(const float4*)(A + (size_t)r * K + k0 + aK)
                                  : make_float4(0.f, 0.f, 0.f, 0.f);
            }
            bReg = *(const float4*)(B + (size_t)(k0 + bRow) * N + col0 + bCol);
        }
        #pragma unroll
        for (int k = 0; k < 16; k++) {
            float4 a0 = *(const float4*)&As[buf][k][ty * 8];
            float4 a1 = *(const float4*)&As[buf][k][ty * 8 + 4];
            float4 b4 = *(const float4*)&Bs[buf][k][tx * 4];
            float a[8] = {a0.x, a0.y, a0.z, a0.w, a1.x, a1.y, a1.z, a1.w};
            float b[4] = {b4.x, b4.y, b4.z, b4.w};
            #pragma unroll
            for (int i = 0; i < 8; i++)
                #pragma unroll
                for (int j = 0; j < 4; j++) acc[i][j] += a[i] * b[j];
        }
        if (nxt < nk) {
            int nb = nxt & 1;
            #pragma unroll
            for (int p = 0; p < 2; p++) {
                int r = aRow + p * 64;
                As[nb][aK + 0][r] = aReg[p].x; As[nb][aK + 1][r] = aReg[p].y;
                As[nb][aK + 2][r] = aReg[p].z; As[nb][aK + 3][r] = aReg[p].w;
            }
            *(float4*)(&Bs[nb][bRow][bCol]) = bReg;
            __syncthreads();
        }
    }

    #pragma unroll
    for (int i = 0; i < 8; i++) {
        int row = row0 + ty * 8 + i;
        if (row < M) {
            float4 o = make_float4(acc[i][0], acc[i][1], acc[i][2], acc[i][3]);
            *(float4*)(C + (size_t)row * N + col0 + tx * 4) = o;
        }
    }
}

// ---------------- attention coefficients ----------------
__global__ void k_alpha1(const float* __restrict__ aw_s, const float* __restrict__ aw_d, int N) {
    int gt = blockIdx.x * blockDim.x + threadIdx.x;
    int n = gt >> 5, lane = gt & 31;
    if (n >= N) return;
    const float* hrow = g_h1 + (size_t)n * 256;
    float ps[4] = {0.f, 0.f, 0.f, 0.f}, pd[4] = {0.f, 0.f, 0.f, 0.f};
    #pragma unroll
    for (int r = 0; r < 8; r++) {
        float v = hrow[r * 32 + lane];
        int h = r >> 1;
        int cc = (r & 1) * 32 + lane;
        ps[h] += v * aw_s[h * 64 + cc];
        pd[h] += v * aw_d[h * 64 + cc];
    }
    #pragma unroll
    for (int h = 0; h < 4; h++) {
        float s = ps[h], d = pd[h];
        #pragma unroll
        for (int off = 16; off; off >>= 1) {
            s += __shfl_xor_sync(0xffffffffu, s, off);
            d += __shfl_xor_sync(0xffffffffu, d, off);
        }
        if (lane == 0) { g_as1[n * 4 + h] = s; g_ad1[n * 4 + h] = d; }
    }
}

__global__ void k_alpha2(const float* __restrict__ aw_s, const float* __restrict__ aw_d, int N) {
    int gt = blockIdx.x * blockDim.x + threadIdx.x;
    int n = gt >> 5, lane = gt & 31;
    if (n >= N) return;
    const float* hrow = g_h2 + (size_t)n * 64;
    float v0 = hrow[lane], v1 = hrow[lane + 32];
    float s = v0 * aw_s[lane] + v1 * aw_s[lane + 32];
    float d = v0 * aw_d[lane] + v1 * aw_d[lane + 32];
    #pragma unroll
    for (int off = 16; off; off >>= 1) {
        s += __shfl_xor_sync(0xffffffffu, s, off);
        d += __shfl_xor_sync(0xffffffffu, d, off);
    }
    if (lane == 0) { g_as2[n] = s; g_ad2[n] = d; }
}

// ---------------- aggregation (warp per dst node, CSR gather, no atomics) ----------------
__global__ void k_agg1(const float* __restrict__ b1, int N) {
    int gt = blockIdx.x * blockDim.x + threadIdx.x;
    int n = gt >> 5, lane = gt & 31;
    if (n >= N) return;
    int h0 = lane >> 4, h1 = h0 + 2;
    float ad0 = g_ad1[n * 4 + h0];
    float ad1v = g_ad1[n * 4 + h1];
    const float4* H = (const float4*)g_h1;
    float4 acc0 = make_float4(0.f, 0.f, 0.f, 0.f), acc1 = acc0;
    float s0 = 0.f, s1 = 0.f;
    int beg = g_rowptr[n], end = g_rowptr[n + 1];
    for (int e = beg - 1; e < end; e++) {            // e == beg-1 -> self loop
        int src = (e < beg) ? n : g_col[e];
        float t0 = g_as1[src * 4 + h0] + ad0;  t0 = (t0 > 0.f) ? t0 : 0.2f * t0;
        float t1 = g_as1[src * 4 + h1] + ad1v; t1 = (t1 > 0.f) ? t1 : 0.2f * t1;
        float x0 = __expf(t0), x1 = __expf(t1);
        float4 v0 = H[(size_t)src * 64 + lane];
        float4 v1 = H[(size_t)src * 64 + 32 + lane];
        acc0.x += x0 * v0.x; acc0.y += x0 * v0.y; acc0.z += x0 * v0.z; acc0.w += x0 * v0.w;
        acc1.x += x1 * v1.x; acc1.y += x1 * v1.y; acc1.z += x1 * v1.z; acc1.w += x1 * v1.w;
        s0 += x0; s1 += x1;
    }
    float i0 = 1.f / s0, i1 = 1.f / s1;
    int c0 = lane * 4, c1 = 128 + lane * 4;
    float4 o0, o1;
    o0.x = fmaxf(acc0.x * i0 + b1[c0 + 0], 0.f);
    o0.y = fmaxf(acc0.y * i0 + b1[c0 + 1], 0.f);
    o0.z = fmaxf(acc0.z * i0 + b1[c0 + 2], 0.f);
    o0.w = fmaxf(acc0.w * i0 + b1[c0 + 3], 0.f);
    o1.x = fmaxf(acc1.x * i1 + b1[c1 + 0], 0.f);
    o1.y = fmaxf(acc1.y * i1 + b1[c1 + 1], 0.f);
    o1.z = fmaxf(acc1.z * i1 + b1[c1 + 2], 0.f);
    o1.w = fmaxf(acc1.w * i1 + b1[c1 + 3], 0.f);
    float4* O = (float4*)g_hrelu;
    O[(size_t)n * 64 + lane] = o0;
    O[(size_t)n * 64 + 32 + lane] = o1;
}

__global__ void k_agg2(const float* __restrict__ b2, float* __restrict__ out, int N) {
    int gt = blockIdx.x * blockDim.x + threadIdx.x;
    int n = gt >> 5, lane = gt & 31;
    if (n >= N) return;
    float ad = g_ad2[n];
    const float2* H = (const float2*)g_h2;
    float2 acc = make_float2(0.f, 0.f);
    float s = 0.f;
    int beg = g_rowptr[n], end = g_rowptr[n + 1];
    for (int e = beg - 1; e < end; e++) {
        int src = (e < beg) ? n : g_col[e];
        float t = g_as2[src] + ad; t = (t > 0.f) ? t : 0.2f * t;
        float x = __expf(t);
        float2 v = H[(size_t)src * 32 + lane];
        acc.x += x * v.x; acc.y += x * v.y;
        s += x;
    }
    float inv = 1.f / s;
    float2 o;
    o.x = acc.x * inv + b2[lane * 2 + 0];
    o.y = acc.y * inv + b2[lane * 2 + 1];
    ((float2*)out)[(size_t)n * 32 + lane] = o;
}

// ---------------- launch ----------------
extern "C" void kernel_launch(void* const* d_in, const int* in_sizes, int n_in,
                              void* d_out, int out_size) {
    const float* x    = (const float*)d_in[0];
    const int*   ei   = (const int*)d_in[1];     // edge_index delivered as int32
    const float* W1   = (const float*)d_in[2];
    const float* as1w = (const float*)d_in[3];
    const float* ad1w = (const float*)d_in[4];
    const float* b1   = (const float*)d_in[5];
    const float* W2   = (const float*)d_in[6];
    const float* as2w = (const float*)d_in[7];
    const float* ad2w = (const float*)d_in[8];
    const float* b2   = (const float*)d_in[9];

    int N = in_sizes[0] / 128;
    int E = in_sizes[1] / 2;
    const int* srcp = ei;
    const int* dstp = ei + E;

    void *p_h1, *p_hrelu, *p_h2;
    cudaGetSymbolAddress(&p_h1, g_h1);
    cudaGetSymbolAddress(&p_hrelu, g_hrelu);
    cudaGetSymbolAddress(&p_h2, g_h2);

    // lazily created side stream + fork/join events (host objects, no device mem)
    static cudaStream_t s2 = nullptr;
    static cudaEvent_t ev_fork = nullptr, ev_join = nullptr;
    if (!s2) {
        cudaStreamCreateWithFlags(&s2, cudaStreamNonBlocking);
        cudaEventCreateWithFlags(&ev_fork, cudaEventDisableTiming);
        cudaEventCreateWithFlags(&ev_join, cudaEventDisableTiming);
    }

    // fork: CSR build runs concurrently with layer-1 GEMM
    cudaEventRecord(ev_fork, 0);
    cudaStreamWaitEvent(s2, ev_fork, 0);
    k_zero_deg<<<(N + 255) / 256, 256, 0, s2>>>(N);
    k_hist<<<(E + 255) / 256, 256, 0, s2>>>(dstp, E, N);
    k_scan<<<1, 1024, 0, s2>>>(N);
    k_scatter<<<(E + 255) / 256, 256, 0, s2>>>(srcp, dstp, E, N);
    cudaEventRecord(ev_join, s2);

    // layer 1 linear + attention coefficients (independent of CSR)
    dim3 g1(256 / 64, (N + 127) / 128);
    k_sgemm<<<g1, 256>>>(x, W1, (float*)p_h1, N, 256, 128);
    k_alpha1<<<(N * 32 + 255) / 256, 256>>>(as1w, ad1w, N);

    // join, then aggregation + layer 2
    cudaStreamWaitEvent(0, ev_join, 0);
    k_agg1<<<(N * 32 + 255) / 256, 256>>>(b1, N);

    dim3 g2(64 / 64, (N + 127) / 128);
    k_sgemm<<<g2, 256>>>((const float*)p_hrelu, W2, (float*)p_h2, N, 64, 256);
    k_alpha2<<<(N * 32 + 255) / 256, 256>>>(as2w, ad2w, N);
    k_agg2<<<(N * 32 + 255) / 256, 256>>>(b2, (float*)d_out, N);
}